// round 2
// baseline (speedup 1.0000x reference)
#include <cuda_runtime.h>

#define B_ 2
#define HW_ 8192
#define D_ 512
#define L_ 4096
#define KN_ 32
#define HEADS_ 8
#define DH_ 64
#define INNER_ 512

// Scratch: device globals (no cudaMalloc allowed).
__device__ float g_q[B_ * HW_ * INNER_];        // 32 MB
__device__ float g_kv[B_ * L_ * 2 * INNER_];    // 32 MB  (k | v split at column 512)
__device__ float g_attn[B_ * HW_ * INNER_];     // 32 MB

// ---------------------------------------------------------------------------
// Classic register-tiled SGEMM: C[M,N] = A[M,K] @ B[K,N] (+ bias row vector)
// BM=BN=128, BK=8, 256 threads, 8x8 per-thread microtile.
// All problem dims here are multiples of 128/8 — no bounds checks.
// ---------------------------------------------------------------------------
__global__ __launch_bounds__(256) void sgemm128(
    const float* __restrict__ A, const float* __restrict__ Bm,
    float* __restrict__ C, int M, int N, int K, const float* __restrict__ bias)
{
    constexpr int BM = 128, BN = 128, BK = 8, TM = 8, TN = 8;
    __shared__ float As[BK][BM];
    __shared__ float Bs[BK][BN];

    const int tid = threadIdx.x;
    const int blockRow = blockIdx.y * BM;
    const int blockCol = blockIdx.x * BN;

    // A tile loaders: 128 rows x 8 cols = 256 float4 (stored transposed)
    const int aRow = tid >> 1;
    const int aCol = (tid & 1) * 4;
    // B tile loaders: 8 rows x 128 cols = 256 float4 (coalesced)
    const int bRow = tid >> 5;
    const int bCol = (tid & 31) * 4;
    // compute mapping: 16x16 threads, each owns 8x8
    const int tr = (tid >> 4) * TM;
    const int tc = (tid & 15) * TN;

    float acc[TM][TN] = {};

    const float* Aptr = A + (size_t)(blockRow + aRow) * K + aCol;
    const float* Bptr = Bm + (size_t)bRow * N + blockCol + bCol;

    for (int k0 = 0; k0 < K; k0 += BK) {
        float4 a4 = *(const float4*)(Aptr + k0);
        As[aCol + 0][aRow] = a4.x;
        As[aCol + 1][aRow] = a4.y;
        As[aCol + 2][aRow] = a4.z;
        As[aCol + 3][aRow] = a4.w;
        *(float4*)&Bs[bRow][bCol] = *(const float4*)(Bptr + (size_t)k0 * N);
        __syncthreads();

        #pragma unroll
        for (int kk = 0; kk < BK; kk++) {
            float ar[TM], br[TN];
            #pragma unroll
            for (int i = 0; i < TM; i++) ar[i] = As[kk][tr + i];
            #pragma unroll
            for (int j = 0; j < TN; j++) br[j] = Bs[kk][tc + j];
            #pragma unroll
            for (int i = 0; i < TM; i++)
                #pragma unroll
                for (int j = 0; j < TN; j++)
                    acc[i][j] = fmaf(ar[i], br[j], acc[i][j]);
        }
        __syncthreads();
    }

    #pragma unroll
    for (int i = 0; i < TM; i++) {
        size_t roff = (size_t)(blockRow + tr + i) * N + blockCol + tc;
        #pragma unroll
        for (int j = 0; j < TN; j += 4) {
            float4 v = make_float4(acc[i][j], acc[i][j + 1], acc[i][j + 2], acc[i][j + 3]);
            if (bias != nullptr) {
                v.x += bias[blockCol + tc + j + 0];
                v.y += bias[blockCol + tc + j + 1];
                v.z += bias[blockCol + tc + j + 2];
                v.w += bias[blockCol + tc + j + 3];
            }
            *(float4*)&C[roff + j] = v;
        }
    }
}

// ---------------------------------------------------------------------------
// Sparse neighbor attention. One block per query (B*HW = 16384 blocks).
// 256 threads = 8 warps, warp h handles head h.
//   Phase 1 (sim): lane j owns neighbor j — 16x LDG.128 from its K row,
//                  q broadcast from shared. sim_j stays in lane j.
//   Softmax: two warp butterfly reductions (max, sum). KN == warp size.
//   Phase 2 (out): lane l owns output dims (2l, 2l+1) — coalesced float2
//                  loads of V rows, p_j broadcast via shuffle.
// ---------------------------------------------------------------------------
__global__ __launch_bounds__(256) void attn_kernel(
    const int* __restrict__ idx, const float* __restrict__ bias)
{
    const int bq   = blockIdx.x;        // 0..B*HW-1
    const int b    = bq >> 13;          // HW = 8192
    const int h    = threadIdx.x >> 5;
    const int lane = threadIdx.x & 31;

    __shared__ float qs[INNER_];
    #pragma unroll
    for (int i = threadIdx.x; i < INNER_; i += 256)
        qs[i] = g_q[(size_t)bq * INNER_ + i];
    __syncthreads();

    // lane == neighbor index (KN_ == 32). idx is int32 (JAX x64 disabled
    // canonicalizes the reference's int64 request to int32). Mask is
    // correctness-neutral insurance: valid indices are already in [0, L).
    const int   row = b * L_ + (idx[(size_t)bq * KN_ + lane] & (L_ - 1));
    const float bj  = bias[(size_t)bq * KN_ + lane];

    const float* krow = g_kv + (size_t)row * (2 * INNER_) + h * DH_;
    float sim = 0.f;
    #pragma unroll
    for (int t = 0; t < DH_; t += 4) {
        float4 k4 = *(const float4*)(krow + t);
        sim = fmaf(qs[h * DH_ + t + 0], k4.x, sim);
        sim = fmaf(qs[h * DH_ + t + 1], k4.y, sim);
        sim = fmaf(qs[h * DH_ + t + 2], k4.z, sim);
        sim = fmaf(qs[h * DH_ + t + 3], k4.w, sim);
    }
    sim = sim * 0.125f + bj;   // SCALE = 64^-0.5

    float m = sim;
    #pragma unroll
    for (int o = 16; o; o >>= 1) m = fmaxf(m, __shfl_xor_sync(0xffffffffu, m, o));
    float e = __expf(sim - m);
    float s = e;
    #pragma unroll
    for (int o = 16; o; o >>= 1) s += __shfl_xor_sync(0xffffffffu, s, o);
    const float p = e / s;

    float2 acc = make_float2(0.f, 0.f);
    const int off = h * DH_ + lane * 2;
    #pragma unroll
    for (int j = 0; j < KN_; j++) {
        const int   rj = __shfl_sync(0xffffffffu, row, j);
        const float pj = __shfl_sync(0xffffffffu, p, j);
        const float2 v2 = *(const float2*)(g_kv + (size_t)rj * (2 * INNER_) + INNER_ + off);
        acc.x = fmaf(pj, v2.x, acc.x);
        acc.y = fmaf(pj, v2.y, acc.y);
    }
    *(float2*)(g_attn + (size_t)bq * INNER_ + off) = acc;
}

// ---------------------------------------------------------------------------
extern "C" void kernel_launch(void* const* d_in, const int* in_sizes, int n_in,
                              void* d_out, int out_size)
{
    const float* x       = (const float*)d_in[0];
    const float* context = (const float*)d_in[1];
    const int*   idx     = (const int*)d_in[2];
    const float* bias    = (const float*)d_in[3];
    const float* Wq      = (const float*)d_in[4];
    const float* Wkv     = (const float*)d_in[5];
    const float* Wo      = (const float*)d_in[6];
    const float* bo      = (const float*)d_in[7];
    float*       out     = (float*)d_out;

    float *pq, *pkv, *pattn;
    cudaGetSymbolAddress((void**)&pq,    g_q);
    cudaGetSymbolAddress((void**)&pkv,   g_kv);
    cudaGetSymbolAddress((void**)&pattn, g_attn);

    const dim3 blk(256);
    // q = x @ Wq                      (16384 x 512) * (512 x 512)
    sgemm128<<<dim3(INNER_ / 128, (B_ * HW_) / 128), blk>>>(
        x, Wq, pq, B_ * HW_, INNER_, D_, nullptr);
    // kv = context @ Wkv              (8192 x 512) * (512 x 1024)
    sgemm128<<<dim3((2 * INNER_) / 128, (B_ * L_) / 128), blk>>>(
        context, Wkv, pkv, B_ * L_, 2 * INNER_, D_, nullptr);
    // sparse attention -> g_attn
    attn_kernel<<<B_ * HW_, blk>>>(idx, bias);
    // out = g_attn @ Wo + bo          (16384 x 512) * (512 x 512)
    sgemm128<<<dim3(D_ / 128, (B_ * HW_) / 128), blk>>>(
        pattn, Wo, out, B_ * HW_, D_, INNER_, bo);
}

// round 3
// speedup vs baseline: 1.4664x; 1.4664x over previous
#include <cuda_runtime.h>
#include <cuda_bf16.h>

#define B_ 2
#define HW_ 8192
#define D_ 512
#define L_ 4096
#define KN_ 32
#define HEADS_ 8
#define DH_ 64
#define INNER_ 512

// Scratch: device globals (no cudaMalloc allowed).
__device__ float g_q[B_ * HW_ * INNER_];
__device__ float g_kv[B_ * L_ * 2 * INNER_];
__device__ float g_attn[B_ * HW_ * INNER_];

// ---------------------------------------------------------------------------
// Tensor-core GEMM with bf16 hi/lo split (3 MMAs -> ~fp32 accuracy).
// C[M,N] = A[M,K] @ B[K,N] (+ optional bias row).
// Block 128x128xBK32, 512 threads = 16 warps in 4x4 grid, warp tile 32x32.
// A smem: [m][k] bf16, padded stride 40 elems (conflict-free ldmatrix).
// B smem: [k][n] bf16, padded stride 136 elems, read via ldmatrix.trans.
// ---------------------------------------------------------------------------
#define AW 20   /* words per A smem row: 16 data + 4 pad (40 bf16) */
#define BW 68   /* words per B smem row: 64 data + 4 pad (136 bf16) */

__device__ __forceinline__ void ldsm_x4(uint4 &r, unsigned addr) {
    asm volatile("ldmatrix.sync.aligned.m8n8.x4.shared.b16 {%0,%1,%2,%3}, [%4];"
        : "=r"(r.x), "=r"(r.y), "=r"(r.z), "=r"(r.w) : "r"(addr));
}
__device__ __forceinline__ void ldsm_x4_t(uint4 &r, unsigned addr) {
    asm volatile("ldmatrix.sync.aligned.m8n8.x4.trans.shared.b16 {%0,%1,%2,%3}, [%4];"
        : "=r"(r.x), "=r"(r.y), "=r"(r.z), "=r"(r.w) : "r"(addr));
}
__device__ __forceinline__ void mma_bf16(float4 &d, const uint4 &a,
                                         unsigned b0, unsigned b1) {
    asm volatile("mma.sync.aligned.m16n8k16.row.col.f32.bf16.bf16.f32 "
        "{%0,%1,%2,%3}, {%4,%5,%6,%7}, {%8,%9}, {%0,%1,%2,%3};"
        : "+f"(d.x), "+f"(d.y), "+f"(d.z), "+f"(d.w)
        : "r"(a.x), "r"(a.y), "r"(a.z), "r"(a.w), "r"(b0), "r"(b1));
}
// pack two floats into bf16x2 hi word + bf16x2 lo word (split representation)
__device__ __forceinline__ void split_pack(float a, float b,
                                           unsigned &whi, unsigned &wlo) {
    __nv_bfloat16 ah = __float2bfloat16(a);
    __nv_bfloat16 bh = __float2bfloat16(b);
    __nv_bfloat16 al = __float2bfloat16(a - __bfloat162float(ah));
    __nv_bfloat16 bl = __float2bfloat16(b - __bfloat162float(bh));
    unsigned short ahu = *(unsigned short*)&ah, bhu = *(unsigned short*)&bh;
    unsigned short alu = *(unsigned short*)&al, blu = *(unsigned short*)&bl;
    whi = ((unsigned)bhu << 16) | ahu;
    wlo = ((unsigned)blu << 16) | alu;
}

__global__ __launch_bounds__(512) void gemm_bf16s(
    const float* __restrict__ A, const float* __restrict__ Bm,
    float* __restrict__ C, int M, int N, int K, const float* __restrict__ bias)
{
    __shared__ unsigned As_hi[128 * AW], As_lo[128 * AW];
    __shared__ unsigned Bs_hi[32 * BW],  Bs_lo[32 * BW];

    const int tid  = threadIdx.x;
    const int lane = tid & 31;
    const int warp = tid >> 5;
    const int wm   = (warp >> 2) * 32;   // warp m offset within block tile
    const int wn   = (warp & 3) * 32;    // warp n offset

    const int blockRow = blockIdx.y * 128;
    const int blockCol = blockIdx.x * 128;

    // --- staging maps ---
    const int aRow = tid >> 3;                 // 0..63 (and +64 for 2nd chunk)
    const int aC4  = (tid & 7) << 2;           // k offset in floats
    const int bK   = tid >> 5;                 // 0..15 (and +16)
    const int bN4  = (tid & 31) << 2;          // n offset in floats

    const float* Ap0 = A + (size_t)(blockRow + aRow) * K + aC4;
    const float* Ap1 = Ap0 + (size_t)64 * K;
    const float* Bp0 = Bm + (size_t)bK * N + blockCol + bN4;
    const float* Bp1 = Bp0 + (size_t)16 * N;

    // --- ldmatrix lane addressing (word offsets) ---
    const int a_l_row = lane & 15;
    const int a_l_k   = (lane >> 4) << 2;              // 0 or 4 words
    const int b_l_k   = (lane & 7) + ((lane >> 4) << 3);
    const int b_l_n   = ((lane >> 3) & 1) << 2;        // 0 or 4 words

    const unsigned ash = (unsigned)__cvta_generic_to_shared(As_hi);
    const unsigned asl = (unsigned)__cvta_generic_to_shared(As_lo);
    const unsigned bsh = (unsigned)__cvta_generic_to_shared(Bs_hi);
    const unsigned bsl = (unsigned)__cvta_generic_to_shared(Bs_lo);

    float4 d[2][4];
    #pragma unroll
    for (int i = 0; i < 2; i++)
        #pragma unroll
        for (int j = 0; j < 4; j++) d[i][j] = make_float4(0.f, 0.f, 0.f, 0.f);

    float4 ar0 = *(const float4*)Ap0;
    float4 ar1 = *(const float4*)Ap1;
    float4 br0 = *(const float4*)Bp0;
    float4 br1 = *(const float4*)Bp1;

    for (int k0 = 0; k0 < K; k0 += 32) {
        // stage registers -> smem (bf16 split)
        {
            unsigned h0, l0, h1, l1;
            split_pack(ar0.x, ar0.y, h0, l0);
            split_pack(ar0.z, ar0.w, h1, l1);
            *(uint2*)&As_hi[aRow * AW + (aC4 >> 1)] = make_uint2(h0, h1);
            *(uint2*)&As_lo[aRow * AW + (aC4 >> 1)] = make_uint2(l0, l1);
            split_pack(ar1.x, ar1.y, h0, l0);
            split_pack(ar1.z, ar1.w, h1, l1);
            *(uint2*)&As_hi[(aRow + 64) * AW + (aC4 >> 1)] = make_uint2(h0, h1);
            *(uint2*)&As_lo[(aRow + 64) * AW + (aC4 >> 1)] = make_uint2(l0, l1);
            split_pack(br0.x, br0.y, h0, l0);
            split_pack(br0.z, br0.w, h1, l1);
            *(uint2*)&Bs_hi[bK * BW + (bN4 >> 1)] = make_uint2(h0, h1);
            *(uint2*)&Bs_lo[bK * BW + (bN4 >> 1)] = make_uint2(l0, l1);
            split_pack(br1.x, br1.y, h0, l0);
            split_pack(br1.z, br1.w, h1, l1);
            *(uint2*)&Bs_hi[(bK + 16) * BW + (bN4 >> 1)] = make_uint2(h0, h1);
            *(uint2*)&Bs_lo[(bK + 16) * BW + (bN4 >> 1)] = make_uint2(l0, l1);
        }
        __syncthreads();

        // prefetch next tile (overlaps with compute below)
        if (k0 + 32 < K) {
            Ap0 += 32; Ap1 += 32;
            Bp0 += (size_t)32 * N; Bp1 += (size_t)32 * N;
            ar0 = *(const float4*)Ap0;
            ar1 = *(const float4*)Ap1;
            br0 = *(const float4*)Bp0;
            br1 = *(const float4*)Bp1;
        }

        // compute: 2 k16 halves
        #pragma unroll
        for (int kk = 0; kk < 2; kk++) {
            uint4 ah[2], al[2], bh[2], bl[2];
            #pragma unroll
            for (int im = 0; im < 2; im++) {
                int w = (wm + im * 16 + a_l_row) * AW + kk * 8 + a_l_k;
                ldsm_x4(ah[im], ash + w * 4);
                ldsm_x4(al[im], asl + w * 4);
            }
            #pragma unroll
            for (int ib = 0; ib < 2; ib++) {
                int w = (kk * 16 + b_l_k) * BW + ((wn + ib * 16) >> 1) + b_l_n;
                ldsm_x4_t(bh[ib], bsh + w * 4);
                ldsm_x4_t(bl[ib], bsl + w * 4);
            }
            #pragma unroll
            for (int im = 0; im < 2; im++)
                #pragma unroll
                for (int ib = 0; ib < 2; ib++) {
                    float4 &d0 = d[im][ib * 2 + 0];
                    float4 &d1 = d[im][ib * 2 + 1];
                    mma_bf16(d0, ah[im], bh[ib].x, bh[ib].z);
                    mma_bf16(d0, ah[im], bl[ib].x, bl[ib].z);
                    mma_bf16(d0, al[im], bh[ib].x, bh[ib].z);
                    mma_bf16(d1, ah[im], bh[ib].y, bh[ib].w);
                    mma_bf16(d1, ah[im], bl[ib].y, bl[ib].w);
                    mma_bf16(d1, al[im], bh[ib].y, bh[ib].w);
                }
        }
        __syncthreads();
    }

    // epilogue
    const int g  = lane >> 2;
    const int t2 = (lane & 3) << 1;
    #pragma unroll
    for (int im = 0; im < 2; im++) {
        const int row0 = blockRow + wm + im * 16 + g;
        #pragma unroll
        for (int j = 0; j < 4; j++) {
            const int col = blockCol + wn + j * 8 + t2;
            float4 v = d[im][j];
            if (bias != nullptr) {
                float b0 = bias[col], b1 = bias[col + 1];
                v.x += b0; v.y += b1; v.z += b0; v.w += b1;
            }
            *(float2*)&C[(size_t)row0 * N + col]       = make_float2(v.x, v.y);
            *(float2*)&C[(size_t)(row0 + 8) * N + col] = make_float2(v.z, v.w);
        }
    }
}

// ---------------------------------------------------------------------------
// Sparse neighbor attention (unchanged from R2-pass version).
// ---------------------------------------------------------------------------
__global__ __launch_bounds__(256) void attn_kernel(
    const int* __restrict__ idx, const float* __restrict__ bias)
{
    const int bq   = blockIdx.x;
    const int b    = bq >> 13;
    const int h    = threadIdx.x >> 5;
    const int lane = threadIdx.x & 31;

    __shared__ float qs[INNER_];
    #pragma unroll
    for (int i = threadIdx.x; i < INNER_; i += 256)
        qs[i] = g_q[(size_t)bq * INNER_ + i];
    __syncthreads();

    const int   row = b * L_ + (idx[(size_t)bq * KN_ + lane] & (L_ - 1));
    const float bj  = bias[(size_t)bq * KN_ + lane];

    const float* krow = g_kv + (size_t)row * (2 * INNER_) + h * DH_;
    float sim = 0.f;
    #pragma unroll
    for (int t = 0; t < DH_; t += 4) {
        float4 k4 = *(const float4*)(krow + t);
        sim = fmaf(qs[h * DH_ + t + 0], k4.x, sim);
        sim = fmaf(qs[h * DH_ + t + 1], k4.y, sim);
        sim = fmaf(qs[h * DH_ + t + 2], k4.z, sim);
        sim = fmaf(qs[h * DH_ + t + 3], k4.w, sim);
    }
    sim = sim * 0.125f + bj;

    float m = sim;
    #pragma unroll
    for (int o = 16; o; o >>= 1) m = fmaxf(m, __shfl_xor_sync(0xffffffffu, m, o));
    float e = __expf(sim - m);
    float s = e;
    #pragma unroll
    for (int o = 16; o; o >>= 1) s += __shfl_xor_sync(0xffffffffu, s, o);
    const float p = e / s;

    float2 acc = make_float2(0.f, 0.f);
    const int off = h * DH_ + lane * 2;
    #pragma unroll
    for (int j = 0; j < KN_; j++) {
        const int   rj = __shfl_sync(0xffffffffu, row, j);
        const float pj = __shfl_sync(0xffffffffu, p, j);
        const float2 v2 = *(const float2*)(g_kv + (size_t)rj * (2 * INNER_) + INNER_ + off);
        acc.x = fmaf(pj, v2.x, acc.x);
        acc.y = fmaf(pj, v2.y, acc.y);
    }
    *(float2*)(g_attn + (size_t)bq * INNER_ + off) = acc;
}

// ---------------------------------------------------------------------------
extern "C" void kernel_launch(void* const* d_in, const int* in_sizes, int n_in,
                              void* d_out, int out_size)
{
    const float* x       = (const float*)d_in[0];
    const float* context = (const float*)d_in[1];
    const int*   idx     = (const int*)d_in[2];
    const float* bias    = (const float*)d_in[3];
    const float* Wq      = (const float*)d_in[4];
    const float* Wkv     = (const float*)d_in[5];
    const float* Wo      = (const float*)d_in[6];
    const float* bo      = (const float*)d_in[7];
    float*       out     = (float*)d_out;

    float *pq, *pkv, *pattn;
    cudaGetSymbolAddress((void**)&pq,    g_q);
    cudaGetSymbolAddress((void**)&pkv,   g_kv);
    cudaGetSymbolAddress((void**)&pattn, g_attn);

    // q = x @ Wq                    (16384 x 512) x (512 x 512)
    gemm_bf16s<<<dim3(INNER_ / 128, (B_ * HW_) / 128), 512>>>(
        x, Wq, pq, B_ * HW_, INNER_, D_, nullptr);
    // kv = context @ Wkv            (8192 x 512) x (512 x 1024)
    gemm_bf16s<<<dim3((2 * INNER_) / 128, (B_ * L_) / 128), 512>>>(
        context, Wkv, pkv, B_ * L_, 2 * INNER_, D_, nullptr);
    // sparse attention -> g_attn
    attn_kernel<<<B_ * HW_, 256>>>(idx, bias);
    // out = attn @ Wo + bo          (16384 x 512) x (512 x 512)
    gemm_bf16s<<<dim3(D_ / 128, (B_ * HW_) / 128), 512>>>(
        pattn, Wo, out, B_ * HW_, D_, INNER_, bo);
}

// round 4
// speedup vs baseline: 1.5601x; 1.0639x over previous
#include <cuda_runtime.h>
#include <cuda_bf16.h>

#define B_ 2
#define HW_ 8192
#define D_ 512
#define L_ 4096
#define KN_ 32
#define HEADS_ 8
#define DH_ 64
#define INNER_ 512
#define MQ (B_ * HW_)   /* 16384 */
#define MC (B_ * L_)    /* 8192  */

// ---------------- device-global scratch (no cudaMalloc allowed) -------------
__device__ float g_q[MQ * INNER_];            // fp32 q (attn consumes fp32)
__device__ float g_kv[MC * 2 * INNER_];       // fp32 kv (attn consumes fp32)
__device__ __nv_bfloat16 g_x_hi[MQ * D_],          g_x_lo[MQ * D_];
__device__ __nv_bfloat16 g_c_hi[MC * D_],          g_c_lo[MC * D_];
__device__ __nv_bfloat16 g_wq_hi[D_ * INNER_],     g_wq_lo[D_ * INNER_];
__device__ __nv_bfloat16 g_wkv_hi[D_ * 2 * INNER_], g_wkv_lo[D_ * 2 * INNER_];
__device__ __nv_bfloat16 g_wo_hi[INNER_ * D_],     g_wo_lo[INNER_ * D_];
__device__ __nv_bfloat16 g_at_hi[MQ * INNER_],     g_at_lo[MQ * INNER_];

// ---------------- helpers ----------------------------------------------------
__device__ __forceinline__ void split_pack(float a, float b,
                                           unsigned &whi, unsigned &wlo) {
    __nv_bfloat16 ah = __float2bfloat16(a);
    __nv_bfloat16 bh = __float2bfloat16(b);
    __nv_bfloat16 al = __float2bfloat16(a - __bfloat162float(ah));
    __nv_bfloat16 bl = __float2bfloat16(b - __bfloat162float(bh));
    unsigned short ahu = *(unsigned short*)&ah, bhu = *(unsigned short*)&bh;
    unsigned short alu = *(unsigned short*)&al, blu = *(unsigned short*)&bl;
    whi = ((unsigned)bhu << 16) | ahu;
    wlo = ((unsigned)blu << 16) | alu;
}

__device__ __forceinline__ void ldsm_x4(uint4 &r, unsigned addr) {
    asm volatile("ldmatrix.sync.aligned.m8n8.x4.shared.b16 {%0,%1,%2,%3}, [%4];"
        : "=r"(r.x), "=r"(r.y), "=r"(r.z), "=r"(r.w) : "r"(addr));
}
__device__ __forceinline__ void ldsm_x4_t(uint4 &r, unsigned addr) {
    asm volatile("ldmatrix.sync.aligned.m8n8.x4.trans.shared.b16 {%0,%1,%2,%3}, [%4];"
        : "=r"(r.x), "=r"(r.y), "=r"(r.z), "=r"(r.w) : "r"(addr));
}
__device__ __forceinline__ void mma_bf16(float4 &d, const uint4 &a,
                                         unsigned b0, unsigned b1) {
    asm volatile("mma.sync.aligned.m16n8k16.row.col.f32.bf16.bf16.f32 "
        "{%0,%1,%2,%3}, {%4,%5,%6,%7}, {%8,%9}, {%0,%1,%2,%3};"
        : "+f"(d.x), "+f"(d.y), "+f"(d.z), "+f"(d.w)
        : "r"(a.x), "r"(a.y), "r"(a.z), "r"(a.w), "r"(b0), "r"(b1));
}
__device__ __forceinline__ void cp16(unsigned saddr, const void* gaddr) {
    asm volatile("cp.async.cg.shared.global [%0], [%1], 16;"
        :: "r"(saddr), "l"(gaddr));
}

// ---------------- fp32 -> bf16 hi/lo split (memory-bound) -------------------
__global__ __launch_bounds__(256) void split_kernel(
    const float4* __restrict__ src, uint2* __restrict__ hi,
    uint2* __restrict__ lo, int n4)
{
    int i = blockIdx.x * 256 + threadIdx.x;
    if (i >= n4) return;
    float4 v = src[i];
    unsigned h0, l0, h1, l1;
    split_pack(v.x, v.y, h0, l0);
    split_pack(v.z, v.w, h1, l1);
    hi[i] = make_uint2(h0, h1);
    lo[i] = make_uint2(l0, l1);
}

// ---------------------------------------------------------------------------
// Tensor-core GEMM, bf16 hi/lo split inputs (pre-converted in global).
// C[M,N] = A[M,K] @ B[K,N] (+ bias). 128x128x32 tiles, 512 thr, 16 warps 4x4,
// warp tile 32x32. 3-stage cp.async pipeline, one __syncthreads per K-tile.
// A smem [m][k] stride 20 words; B smem [k][n] stride 68 words (padded,
// conflict-free ldmatrix) — identical compute path to the verified R3 kernel.
// ---------------------------------------------------------------------------
#define AW 20
#define BW 68
#define STG_W 9472            /* words per stage: 2*2560 (A) + 2*2176 (B) */
#define SMEM_BYTES (3 * STG_W * 4)

__global__ __launch_bounds__(512) void gemm_bf16s(
    const __nv_bfloat16* __restrict__ Ah, const __nv_bfloat16* __restrict__ Al,
    const __nv_bfloat16* __restrict__ Bh, const __nv_bfloat16* __restrict__ Bl,
    float* __restrict__ C, int M, int N, int K, const float* __restrict__ bias)
{
    extern __shared__ unsigned sm[];
    const unsigned smbase = (unsigned)__cvta_generic_to_shared(sm);

    const int tid  = threadIdx.x;
    const int lane = tid & 31;
    const int warp = tid >> 5;
    const int wm   = (warp >> 2) * 32;
    const int wn   = (warp & 3) * 32;
    const int blockRow = blockIdx.y * 128;
    const int blockCol = blockIdx.x * 128;

    // cp.async loader map: A 128 rows x 4 chunks, B 32 rows x 16 chunks
    const int ar = tid >> 2, ac = tid & 3;
    const int bk = tid >> 4, bc = tid & 15;
    const __nv_bfloat16* gAh = Ah + (size_t)(blockRow + ar) * K + ac * 8;
    const __nv_bfloat16* gAl = Al + (size_t)(blockRow + ar) * K + ac * 8;
    const __nv_bfloat16* gBh = Bh + (size_t)bk * N + blockCol + bc * 8;
    const __nv_bfloat16* gBl = Bl + (size_t)bk * N + blockCol + bc * 8;
    const unsigned a_sb = ar * 80 + ac * 16;    // byte offset in stage
    const unsigned b_sb = bk * 272 + bc * 16;

    // ldmatrix lane maps (word offsets) — same as verified kernel
    const int a_l_row = lane & 15;
    const int a_l_k   = (lane >> 4) << 2;
    const int b_l_k   = (lane & 7) + ((lane >> 4) << 3);
    const int b_l_n   = ((lane >> 3) & 1) << 2;

    float4 d[2][4];
    #pragma unroll
    for (int i = 0; i < 2; i++)
        #pragma unroll
        for (int j = 0; j < 4; j++) d[i][j] = make_float4(0.f, 0.f, 0.f, 0.f);

    auto issue = [&](int stage, int k0) {
        unsigned s = smbase + stage * (STG_W * 4);
        cp16(s + a_sb,               gAh + k0);
        cp16(s + 2560 * 4 + a_sb,    gAl + k0);
        cp16(s + 5120 * 4 + b_sb,    gBh + (size_t)k0 * N);
        cp16(s + 7296 * 4 + b_sb,    gBl + (size_t)k0 * N);
    };

    // prologue: stages 0,1 in flight
    issue(0, 0);
    asm volatile("cp.async.commit_group;" ::: "memory");
    issue(1, 32);
    asm volatile("cp.async.commit_group;" ::: "memory");
    asm volatile("cp.async.wait_group 1;" ::: "memory");
    __syncthreads();

    const int nK = K >> 5;
    for (int i = 0; i < nK; i++) {
        const int stage = i % 3;
        const int kn = (i + 2) << 5;
        if (kn < K) issue((i + 2) % 3, kn);
        asm volatile("cp.async.commit_group;" ::: "memory");

        const unsigned sb = smbase + stage * (STG_W * 4);
        #pragma unroll
        for (int kk = 0; kk < 2; kk++) {
            uint4 ah[2], al[2];
            #pragma unroll
            for (int im = 0; im < 2; im++) {
                unsigned w = ((wm + im * 16 + a_l_row) * AW + kk * 8 + a_l_k) * 4;
                ldsm_x4(ah[im], sb + w);
                ldsm_x4(al[im], sb + 2560 * 4 + w);
            }
            #pragma unroll
            for (int ib = 0; ib < 2; ib++) {
                uint4 bh, bl;
                unsigned w = ((kk * 16 + b_l_k) * BW + ((wn + ib * 16) >> 1) + b_l_n) * 4;
                ldsm_x4_t(bh, sb + 5120 * 4 + w);
                ldsm_x4_t(bl, sb + 7296 * 4 + w);
                #pragma unroll
                for (int im = 0; im < 2; im++) {
                    float4 &d0 = d[im][ib * 2 + 0];
                    float4 &d1 = d[im][ib * 2 + 1];
                    mma_bf16(d0, ah[im], bh.x, bh.z);
                    mma_bf16(d0, ah[im], bl.x, bl.z);
                    mma_bf16(d0, al[im], bh.x, bh.z);
                    mma_bf16(d1, ah[im], bh.y, bh.w);
                    mma_bf16(d1, ah[im], bl.y, bl.w);
                    mma_bf16(d1, al[im], bh.y, bh.w);
                }
            }
        }
        asm volatile("cp.async.wait_group 1;" ::: "memory");
        __syncthreads();
    }

    // epilogue
    const int g  = lane >> 2;
    const int t2 = (lane & 3) << 1;
    #pragma unroll
    for (int im = 0; im < 2; im++) {
        const int row0 = blockRow + wm + im * 16 + g;
        #pragma unroll
        for (int j = 0; j < 4; j++) {
            const int col = blockCol + wn + j * 8 + t2;
            float4 v = d[im][j];
            if (bias != nullptr) {
                float b0 = bias[col], b1 = bias[col + 1];
                v.x += b0; v.y += b1; v.z += b0; v.w += b1;
            }
            *(float2*)&C[(size_t)row0 * N + col]       = make_float2(v.x, v.y);
            *(float2*)&C[(size_t)(row0 + 8) * N + col] = make_float2(v.z, v.w);
        }
    }
}

// ---------------------------------------------------------------------------
// Sparse neighbor attention. Writes output directly as bf16 hi/lo split.
// ---------------------------------------------------------------------------
__global__ __launch_bounds__(256) void attn_kernel(
    const int* __restrict__ idx, const float* __restrict__ bias)
{
    const int bq   = blockIdx.x;
    const int b    = bq >> 13;
    const int h    = threadIdx.x >> 5;
    const int lane = threadIdx.x & 31;

    __shared__ float qs[INNER_];
    #pragma unroll
    for (int i = threadIdx.x; i < INNER_; i += 256)
        qs[i] = g_q[(size_t)bq * INNER_ + i];
    __syncthreads();

    const int   row = b * L_ + (idx[(size_t)bq * KN_ + lane] & (L_ - 1));
    const float bj  = bias[(size_t)bq * KN_ + lane];

    const float* krow = g_kv + (size_t)row * (2 * INNER_) + h * DH_;
    float sim = 0.f;
    #pragma unroll
    for (int t = 0; t < DH_; t += 4) {
        float4 k4 = *(const float4*)(krow + t);
        sim = fmaf(qs[h * DH_ + t + 0], k4.x, sim);
        sim = fmaf(qs[h * DH_ + t + 1], k4.y, sim);
        sim = fmaf(qs[h * DH_ + t + 2], k4.z, sim);
        sim = fmaf(qs[h * DH_ + t + 3], k4.w, sim);
    }
    sim = sim * 0.125f + bj;

    float m = sim;
    #pragma unroll
    for (int o = 16; o; o >>= 1) m = fmaxf(m, __shfl_xor_sync(0xffffffffu, m, o));
    float e = __expf(sim - m);
    float s = e;
    #pragma unroll
    for (int o = 16; o; o >>= 1) s += __shfl_xor_sync(0xffffffffu, s, o);
    const float p = e / s;

    float2 acc = make_float2(0.f, 0.f);
    const int off = h * DH_ + lane * 2;
    #pragma unroll
    for (int j = 0; j < KN_; j++) {
        const int   rj = __shfl_sync(0xffffffffu, row, j);
        const float pj = __shfl_sync(0xffffffffu, p, j);
        const float2 v2 = *(const float2*)(g_kv + (size_t)rj * (2 * INNER_) + INNER_ + off);
        acc.x = fmaf(pj, v2.x, acc.x);
        acc.y = fmaf(pj, v2.y, acc.y);
    }
    unsigned whi, wlo;
    split_pack(acc.x, acc.y, whi, wlo);
    const size_t widx = ((size_t)bq * INNER_ + off) >> 1;
    ((unsigned*)g_at_hi)[widx] = whi;
    ((unsigned*)g_at_lo)[widx] = wlo;
}

// ---------------------------------------------------------------------------
extern "C" void kernel_launch(void* const* d_in, const int* in_sizes, int n_in,
                              void* d_out, int out_size)
{
    const float* x       = (const float*)d_in[0];
    const float* context = (const float*)d_in[1];
    const int*   idx     = (const int*)d_in[2];
    const float* bias    = (const float*)d_in[3];
    const float* Wq      = (const float*)d_in[4];
    const float* Wkv     = (const float*)d_in[5];
    const float* Wo      = (const float*)d_in[6];
    const float* bo      = (const float*)d_in[7];
    float*       out     = (float*)d_out;

    float *pq, *pkv;
    __nv_bfloat16 *xh, *xl, *ch, *cl, *qh, *ql, *kh, *kl, *oh, *ol, *ath, *atl;
    cudaGetSymbolAddress((void**)&pq,  g_q);
    cudaGetSymbolAddress((void**)&pkv, g_kv);
    cudaGetSymbolAddress((void**)&xh,  g_x_hi);   cudaGetSymbolAddress((void**)&xl,  g_x_lo);
    cudaGetSymbolAddress((void**)&ch,  g_c_hi);   cudaGetSymbolAddress((void**)&cl,  g_c_lo);
    cudaGetSymbolAddress((void**)&qh,  g_wq_hi);  cudaGetSymbolAddress((void**)&ql,  g_wq_lo);
    cudaGetSymbolAddress((void**)&kh,  g_wkv_hi); cudaGetSymbolAddress((void**)&kl,  g_wkv_lo);
    cudaGetSymbolAddress((void**)&oh,  g_wo_hi);  cudaGetSymbolAddress((void**)&ol,  g_wo_lo);
    cudaGetSymbolAddress((void**)&ath, g_at_hi);  cudaGetSymbolAddress((void**)&atl, g_at_lo);

    cudaFuncSetAttribute(gemm_bf16s,
        cudaFuncAttributeMaxDynamicSharedMemorySize, SMEM_BYTES);

    // split inputs to bf16 hi/lo
    auto splt = [&](const float* s, __nv_bfloat16* h, __nv_bfloat16* l, int n) {
        split_kernel<<<(n / 4 + 255) / 256, 256>>>(
            (const float4*)s, (uint2*)h, (uint2*)l, n / 4);
    };
    splt(x,       xh, xl, MQ * D_);
    splt(context, ch, cl, MC * D_);
    splt(Wq,      qh, ql, D_ * INNER_);
    splt(Wkv,     kh, kl, D_ * 2 * INNER_);
    splt(Wo,      oh, ol, INNER_ * D_);

    // q = x @ Wq
    gemm_bf16s<<<dim3(INNER_ / 128, MQ / 128), 512, SMEM_BYTES>>>(
        xh, xl, qh, ql, pq, MQ, INNER_, D_, nullptr);
    // kv = context @ Wkv
    gemm_bf16s<<<dim3((2 * INNER_) / 128, MC / 128), 512, SMEM_BYTES>>>(
        ch, cl, kh, kl, pkv, MC, 2 * INNER_, D_, nullptr);
    // sparse attention -> split bf16 attn matrix
    attn_kernel<<<MQ, 256>>>(idx, bias);
    // out = attn @ Wo + bo
    gemm_bf16s<<<dim3(D_ / 128, MQ / 128), 512, SMEM_BYTES>>>(
        ath, atl, oh, ol, out, MQ, D_, INNER_, bo);
}